// round 2
// baseline (speedup 1.0000x reference)
#include <cuda_runtime.h>
#include <math.h>

#define BB   4
#define CC   256
#define HH   128
#define WWp  128
#define HWS  16384      // HH*WWp
#define HEADS 8
#define CHD  32         // CC/HEADS

// ---------------- scratch (device globals; no allocation) ----------------
__device__ float g_xn[BB*CC*HWS];
__device__ float g_yn[BB*CC*HWS];
__device__ float g_kv[BB*2*CC*HWS];
__device__ float g_kv2[BB*2*CC*HWS];
__device__ float g_q[BB*CC*HWS];
__device__ float g_av[BB*CC*HWS];
__device__ float g_invq[BB*CC];
__device__ float g_invk[BB*CC];
__device__ float g_attn_part[8][BB*HEADS*CHD*CHD];
__device__ float g_attn[BB*HEADS*CHD*CHD];

// ---------------- 1. LayerNorm over channel dim (per pixel) ----------------
__global__ void ln_kernel(const float* __restrict__ x, const float* __restrict__ y,
                          const float* __restrict__ wkv, const float* __restrict__ bkv,
                          const float* __restrict__ wq,  const float* __restrict__ bq)
{
    int idx = blockIdx.x*blockDim.x + threadIdx.x;   // 0..65535 (b*HWS+p)
    int b = idx >> 14;
    int p = idx & (HWS-1);
    const float* src; float* dst; const float* wv; const float* bv;
    if (blockIdx.y == 0) { src=x; dst=g_xn; wv=wkv; bv=bkv; }
    else                 { src=y; dst=g_yn; wv=wq;  bv=bq;  }
    size_t base = (size_t)b*CC*HWS + p;
    float s=0.f, s2=0.f;
    #pragma unroll 8
    for (int c=0;c<CC;c++){ float v = src[base + (size_t)c*HWS]; s+=v; s2+=v*v; }
    float mu  = s  * (1.f/CC);
    float var = s2 * (1.f/CC) - mu*mu;
    float rs  = rsqrtf(var + 1e-5f);
    #pragma unroll 8
    for (int c=0;c<CC;c++){
        float v = src[base + (size_t)c*HWS];
        dst[base + (size_t)c*HWS] = (v-mu)*rs*wv[c] + bv[c];
    }
}

// ---------------- 2. tiled SGEMM for 1x1 convs ----------------
// out[b, m, n] = sum_k A[m,k] * X[b,k,n]  (+ resid)
template<int M, bool RESID>
__global__ void __launch_bounds__(256) gemm1x1(const float* __restrict__ A,
                                               const float* __restrict__ X,
                                               const float* __restrict__ R,
                                               float* __restrict__ out)
{
    __shared__ float As[16][65];
    __shared__ float Bs[16][64];
    int b  = blockIdx.z;
    int m0 = blockIdx.y*64;
    int n0 = blockIdx.x*64;
    const float* Xb = X + (size_t)b*CC*HWS;
    int tid = threadIdx.x;
    int ty = tid>>4, tx = tid&15;
    float acc[4][4] = {};
    for (int k0=0;k0<CC;k0+=16){
        {   // A tile: As[k][m]
            int kk = tid & 15, mb = tid >> 4;
            #pragma unroll
            for (int it=0; it<4; it++){
                int m = mb + it*16;
                As[kk][m] = A[(size_t)(m0+m)*CC + k0+kk];
            }
        }
        {   // B tile: Bs[k][n]
            int col = tid & 63, kb = tid >> 6;
            #pragma unroll
            for (int it=0; it<4; it++){
                int kk = kb + it*4;
                Bs[kk][col] = Xb[(size_t)(k0+kk)*HWS + n0+col];
            }
        }
        __syncthreads();
        #pragma unroll
        for (int kk=0;kk<16;kk++){
            float a[4], bf[4];
            #pragma unroll
            for (int i=0;i<4;i++) a[i]=As[kk][ty*4+i];
            #pragma unroll
            for (int j=0;j<4;j++) bf[j]=Bs[kk][tx*4+j];
            #pragma unroll
            for (int i=0;i<4;i++)
                #pragma unroll
                for (int j=0;j<4;j++) acc[i][j] += a[i]*bf[j];
        }
        __syncthreads();
    }
    #pragma unroll
    for (int i=0;i<4;i++){
        int row = m0+ty*4+i;
        size_t rb = ((size_t)b*M + row)*HWS + n0 + tx*4;
        float4 v = make_float4(acc[i][0],acc[i][1],acc[i][2],acc[i][3]);
        if (RESID){
            float4 r = *(const float4*)&R[rb];
            v.x+=r.x; v.y+=r.y; v.z+=r.z; v.w+=r.w;
        }
        *(float4*)&out[rb] = v;
    }
}

// ---------------- 3. depthwise 3x3 (SAME) on kv ----------------
__global__ void dw_kernel(const float* __restrict__ Wdw)
{
    int idx = blockIdx.x*256 + threadIdx.x;  // over BB*512*HWS
    int p  = idx & (HWS-1);
    int bc = idx >> 14;                      // b*512 + ch
    int ch = bc & 511;
    int x = p & (WWp-1), y = p >> 7;
    const float* w  = Wdw + ch*9;
    const float* in = g_kv + (size_t)bc*HWS;
    float acc = 0.f;
    for (int dy=-1;dy<=1;dy++){
        int yy=y+dy; if (yy<0||yy>=HH) continue;
        for (int dx=-1;dx<=1;dx++){
            int xx=x+dx; if (xx<0||xx>=WWp) continue;
            acc += __ldg(&w[(dy+1)*3+dx+1]) * in[yy*WWp+xx];
        }
    }
    g_kv2[(size_t)bc*HWS + p] = acc;
}

// ---------------- 4. q = 3x3 conv (implicit GEMM) ----------------
__global__ void __launch_bounds__(256) qconv_kernel(const float* __restrict__ Wq)
{
    __shared__ float Bs[16][68];        // 16 channels x 66 cols (+pad)
    __shared__ float As[3][16][64];     // tap x channel x co
    int b   = blockIdx.z;
    int co0 = blockIdx.y*64;
    int y   = blockIdx.x >> 1;
    int x0  = (blockIdx.x & 1)*64;
    int tid = threadIdx.x;
    int ty = tid>>4, tx = tid&15;
    float acc[4][4] = {};
    const float* Yb = g_yn + (size_t)b*CC*HWS;
    for (int dy=-1;dy<=1;dy++){
        int yy = y+dy;
        if (yy<0||yy>=HH) continue;     // uniform across block
        for (int c0=0;c0<CC;c0+=16){
            for (int idx=tid; idx<16*66; idx+=256){
                int cc = idx/66, col = idx%66;
                int gx = x0-1+col;
                float v = 0.f;
                if (gx>=0 && gx<WWp)
                    v = Yb[((size_t)(c0+cc)*HH + yy)*WWp + gx];
                Bs[cc][col]=v;
            }
            for (int idx=tid; idx<3*16*64; idx+=256){
                int dx  = idx>>10;
                int rem = idx & 1023;
                int cc  = rem>>6, m = rem&63;
                As[dx][cc][m] = Wq[((size_t)(co0+m)*CC + c0+cc)*9 + (dy+1)*3 + dx];
            }
            __syncthreads();
            #pragma unroll 4
            for (int cc=0;cc<16;cc++){
                float bb[6];
                #pragma unroll
                for (int j=0;j<6;j++) bb[j]=Bs[cc][tx*4+j];
                #pragma unroll
                for (int dx=0;dx<3;dx++){
                    float a[4];
                    #pragma unroll
                    for (int i=0;i<4;i++) a[i]=As[dx][cc][ty*4+i];
                    #pragma unroll
                    for (int i=0;i<4;i++)
                        #pragma unroll
                        for (int j=0;j<4;j++)
                            acc[i][j] += a[i]*bb[j+dx];
                }
            }
            __syncthreads();
        }
    }
    #pragma unroll
    for (int i=0;i<4;i++){
        int co = co0+ty*4+i;
        size_t base = ((size_t)(b*CC+co)*HH + y)*WWp + x0 + tx*4;
        *(float4*)&g_q[base] = make_float4(acc[i][0],acc[i][1],acc[i][2],acc[i][3]);
    }
}

// ---------------- 5. per-channel L2 norms of q and k ----------------
__global__ void norm_kernel()
{
    int bc = blockIdx.x;             // 0..1023 (b*256+c)
    bool isq = (blockIdx.y==0);
    int b = bc >> 8, c = bc & 255;
    const float* src = isq ? (g_q   + ((size_t)b*CC   + c)*HWS)
                           : (g_kv2 + ((size_t)b*2*CC + c)*HWS);
    float s=0.f;
    for (int i=threadIdx.x; i<HWS; i+=256){ float v=src[i]; s+=v*v; }
    __shared__ float red[8];
    for (int o=16;o>0;o>>=1) s += __shfl_xor_sync(0xffffffffu, s, o);
    if ((threadIdx.x&31)==0) red[threadIdx.x>>5]=s;
    __syncthreads();
    if (threadIdx.x<8){
        float v = red[threadIdx.x];
        for (int o=4;o>0;o>>=1) v += __shfl_xor_sync(0x000000ffu, v, o);
        if (threadIdx.x==0)
            (isq?g_invq:g_invk)[bc] = 1.f / fmaxf(sqrtf(v), 1e-12f);
    }
}

// ---------------- 6. attention scores: split-K QK^T partials ----------------
__global__ void __launch_bounds__(256) attn_part_kernel()
{
    __shared__ float Qs[CHD][65];
    __shared__ float Kt[64][33];
    int bh = blockIdx.y;             // 0..31
    int b = bh >> 3, h = bh & 7;
    int split = blockIdx.x;          // 0..7
    int n0 = split*2048;
    const float* Qb = g_q   + ((size_t)b*CC   + h*CHD)*HWS;
    const float* Kb = g_kv2 + ((size_t)b*2*CC + h*CHD)*HWS;
    int tid = threadIdx.x;
    int i = tid>>3, jq = tid&7;
    float acc[4]={};
    for (int nc=0;nc<2048;nc+=64){
        for (int idx=tid; idx<2048; idx+=256){
            int r = idx>>6, col = idx&63;
            float qv = Qb[(size_t)r*HWS + n0+nc+col];
            float kv = Kb[(size_t)r*HWS + n0+nc+col];
            Qs[r][col] = qv;
            Kt[col][r] = kv;
        }
        __syncthreads();
        #pragma unroll 8
        for (int cc=0;cc<64;cc++){
            float qv = Qs[i][cc];
            #pragma unroll
            for (int jj=0;jj<4;jj++) acc[jj] += qv * Kt[cc][jq*4+jj];
        }
        __syncthreads();
    }
    #pragma unroll
    for (int jj=0;jj<4;jj++)
        g_attn_part[split][bh*CHD*CHD + i*CHD + jq*4+jj] = acc[jj];
}

// ---------------- 7. combine partials, scale, softmax over d ----------------
__global__ void softmax_kernel(const float* __restrict__ temp)
{
    int bh = blockIdx.x;             // 32 blocks x 1024 threads
    int b = bh>>3, h = bh&7;
    int tid = threadIdx.x;
    int i = tid>>5, j = tid&31;
    float v = 0.f;
    #pragma unroll
    for (int s=0;s<8;s++) v += g_attn_part[s][bh*1024 + i*32 + j];
    v *= g_invq[b*CC + h*CHD + i] * g_invk[b*CC + h*CHD + j] * temp[h];
    float m = v;
    for (int o=16;o>0;o>>=1) m = fmaxf(m, __shfl_xor_sync(0xffffffffu, m, o));
    float e = expf(v - m);
    float s = e;
    for (int o=16;o>0;o>>=1) s += __shfl_xor_sync(0xffffffffu, s, o);
    g_attn[bh*1024 + i*32 + j] = e / s;
}

// ---------------- 8. out = attn @ v ----------------
__global__ void __launch_bounds__(128) av_kernel()
{
    __shared__ float A[CHD][CHD];
    int bh = blockIdx.y; int b=bh>>3, h=bh&7;
    int n0 = blockIdx.x*128;
    int tid = threadIdx.x;
    for (int idx=tid; idx<CHD*CHD; idx+=128) ((float*)A)[idx] = g_attn[bh*1024+idx];
    __syncthreads();
    const float* Vb = g_kv2 + ((size_t)b*2*CC + CC + h*CHD)*HWS;
    float accv[CHD];
    #pragma unroll
    for (int i=0;i<CHD;i++) accv[i]=0.f;
    int n = n0 + tid;
    #pragma unroll 4
    for (int j=0;j<CHD;j++){
        float vj = Vb[(size_t)j*HWS + n];
        #pragma unroll
        for (int i=0;i<CHD;i++) accv[i] += A[i][j]*vj;
    }
    float* Ob = g_av + ((size_t)b*CC + h*CHD)*HWS;
    #pragma unroll
    for (int i=0;i<CHD;i++) Ob[(size_t)i*HWS + n] = accv[i];
}

// ---------------- launch ----------------
extern "C" void kernel_launch(void* const* d_in, const int* in_sizes, int n_in,
                              void* d_out, int out_size)
{
    const float* x       = (const float*)d_in[0];
    const float* y       = (const float*)d_in[1];
    const float* ln_kv_w = (const float*)d_in[2];
    const float* ln_kv_b = (const float*)d_in[3];
    const float* ln_q_w  = (const float*)d_in[4];
    const float* ln_q_b  = (const float*)d_in[5];
    const float* W_kv    = (const float*)d_in[6];
    const float* W_dw    = (const float*)d_in[7];
    const float* W_q     = (const float*)d_in[8];
    const float* W_proj  = (const float*)d_in[9];
    const float* temp    = (const float*)d_in[10];
    float* out = (float*)d_out;

    float *p_xn, *p_kv, *p_av, *p_yn;
    cudaGetSymbolAddress((void**)&p_xn, g_xn);
    cudaGetSymbolAddress((void**)&p_kv, g_kv);
    cudaGetSymbolAddress((void**)&p_av, g_av);
    cudaGetSymbolAddress((void**)&p_yn, g_yn);

    ln_kernel<<<dim3(256,2), 256>>>(x, y, ln_kv_w, ln_kv_b, ln_q_w, ln_q_b);
    gemm1x1<512,false><<<dim3(256,8,4), 256>>>(W_kv, p_xn, nullptr, p_kv);
    dw_kernel<<<131072, 256>>>(W_dw);
    qconv_kernel<<<dim3(256,4,4), 256>>>(W_q);
    norm_kernel<<<dim3(1024,2), 256>>>();
    attn_part_kernel<<<dim3(8,32), 256>>>();
    softmax_kernel<<<32, 1024>>>(temp);
    av_kernel<<<dim3(128,32), 128>>>();
    gemm1x1<256,true><<<dim3(256,4,4), 256>>>(W_proj, p_av, p_yn, out);
}

// round 6
// speedup vs baseline: 2.4878x; 2.4878x over previous
#include <cuda_runtime.h>
#include <cuda_bf16.h>
#include <cstdint>
#include <math.h>

#define BB   4
#define CC   256
#define HH   128
#define WWp  128
#define HWS  16384      // HH*WWp
#define HEADS 8
#define CHD  32         // CC/HEADS
#define KQ   2304       // 9*CC for 3x3 conv as GEMM

// ---------------- scratch (device globals; no allocation) ----------------
__device__ __nv_bfloat16 g_xn [BB*CC*HWS];          // LN(x) in bf16 (kv GEMM B)
__device__ float         g_yn [BB*CC*HWS];          // LN(y) fp32 (residual + shifts)
__device__ __nv_bfloat16 g_imq[(size_t)BB*KQ*HWS];  // 9 shifted copies of yn (q GEMM B)
__device__ float         g_kv [BB*2*CC*HWS];        // kv conv out fp32
__device__ float         g_kv2[BB*2*CC*HWS];        // after depthwise
__device__ float         g_q  [BB*CC*HWS];          // q conv out fp32
__device__ __nv_bfloat16 g_avb[BB*CC*HWS];          // attn@v in bf16 (proj GEMM B)
__device__ float g_invq[BB*CC];
__device__ float g_invk[BB*CC];
__device__ float g_attn_part[8][BB*HEADS*CHD*CHD];
__device__ float g_attn[BB*HEADS*CHD*CHD];
// bf16 weights
__device__ __nv_bfloat16 g_Wkv[2*CC*CC];
__device__ __nv_bfloat16 g_Wq [CC*KQ];
__device__ __nv_bfloat16 g_Wp [CC*CC];

// ---------------- helpers ----------------
__device__ __forceinline__ uint32_t smem_u32(const void* p){
    uint32_t a;
    asm("{ .reg .u64 t; cvta.to.shared.u64 t, %1; cvt.u32.u64 %0, t; }" : "=r"(a) : "l"(p));
    return a;
}
#define SWZ(o) ((o) ^ (((o)>>3)&0x70))
#define CP_ASYNC16(dst, src) \
    asm volatile("cp.async.cg.shared.global [%0], [%1], 16;" :: "r"(dst), "l"(src))
#define CP_COMMIT() asm volatile("cp.async.commit_group;" ::: "memory")
#define CP_WAIT1()  asm volatile("cp.async.wait_group 1;" ::: "memory")
#define CP_WAIT0()  asm volatile("cp.async.wait_group 0;" ::: "memory")
#define MMA16816(c, a, b0, b1) \
    asm volatile("mma.sync.aligned.m16n8k16.row.col.f32.bf16.bf16.f32 " \
        "{%0,%1,%2,%3}, {%4,%5,%6,%7}, {%8,%9}, {%0,%1,%2,%3};" \
        : "+f"((c)[0]), "+f"((c)[1]), "+f"((c)[2]), "+f"((c)[3]) \
        : "r"((a)[0]), "r"((a)[1]), "r"((a)[2]), "r"((a)[3]), "r"(b0), "r"(b1))

// ---------------- 0. weight convert / reorder to bf16 ----------------
__global__ void convw_kernel(const float* __restrict__ Wkv, const float* __restrict__ Wq,
                             const float* __restrict__ Wp)
{
    int i = blockIdx.x*256 + threadIdx.x;
    if (i < 2*CC*CC) {                       // W_kv [512][256]
        g_Wkv[i] = __float2bfloat16(Wkv[i]);
    } else if (i < 2*CC*CC + CC*KQ) {        // W_q [256][256][3][3] -> [co][t*256+ci]
        int j = i - 2*CC*CC;
        int co = j / KQ, r = j % KQ;
        int t = r >> 8, ci = r & 255;
        g_Wq[j] = __float2bfloat16(Wq[((size_t)(co*CC+ci))*9 + t]);
    } else if (i < 2*CC*CC + CC*KQ + CC*CC) {
        int j = i - (2*CC*CC + CC*KQ);
        g_Wp[j] = __float2bfloat16(Wp[j]);
    }
}

// ---------------- 1. LayerNorm over channel dim ----------------
__global__ void ln_kernel(const float* __restrict__ x, const float* __restrict__ y,
                          const float* __restrict__ wkv, const float* __restrict__ bkv,
                          const float* __restrict__ wq,  const float* __restrict__ bq)
{
    int idx = blockIdx.x*blockDim.x + threadIdx.x;
    int b = idx >> 14;
    int p = idx & (HWS-1);
    size_t base = (size_t)b*CC*HWS + p;
    if (blockIdx.y == 0) {
        float s=0.f, s2=0.f;
        #pragma unroll 8
        for (int c=0;c<CC;c++){ float v = x[base + (size_t)c*HWS]; s+=v; s2+=v*v; }
        float mu = s*(1.f/CC), var = s2*(1.f/CC)-mu*mu, rs = rsqrtf(var+1e-5f);
        #pragma unroll 8
        for (int c=0;c<CC;c++){
            float v = x[base + (size_t)c*HWS];
            g_xn[base + (size_t)c*HWS] = __float2bfloat16((v-mu)*rs*wkv[c]+bkv[c]);
        }
    } else {
        float s=0.f, s2=0.f;
        #pragma unroll 8
        for (int c=0;c<CC;c++){ float v = y[base + (size_t)c*HWS]; s+=v; s2+=v*v; }
        float mu = s*(1.f/CC), var = s2*(1.f/CC)-mu*mu, rs = rsqrtf(var+1e-5f);
        #pragma unroll 8
        for (int c=0;c<CC;c++){
            float v = y[base + (size_t)c*HWS];
            g_yn[base + (size_t)c*HWS] = (v-mu)*rs*wq[c]+bq[c];
        }
    }
}

// ---------------- 2. build 9 shifted bf16 copies of yn (im2col) ----------------
__global__ void shift9_kernel()
{
    int p  = blockIdx.x*256 + threadIdx.x;        // pixel
    int t  = blockIdx.y >> 8;                     // tap 0..8 (kh*3+kw)
    int ci = blockIdx.y & 255;
    int b  = blockIdx.z;
    int yy = (p >> 7) + (t/3) - 1;
    int xx = (p & 127) + (t%3) - 1;
    float v = 0.f;
    if (yy>=0 && yy<HH && xx>=0 && xx<WWp)
        v = g_yn[(((size_t)b*CC + ci)<<14) + (yy<<7) + xx];
    g_imq[(((size_t)b*KQ + t*CC + ci)<<14) + p] = __float2bfloat16(v);
}

// ---------------- 3. HMMA bf16 GEMM: out[b,m,n] = sum_k A[m,k]*B[b,k,n] (+R) ------
// CTA tile: M=128, N=64, K chunk 64, double-buffered cp.async, 8 warps of 32x32.
// A smem: [128 m][64 k] bf16, 128B rows, SW128 swizzle.
// B smem: [64 k][64 n] bf16, 128B rows, SW128 swizzle.
__global__ void __launch_bounds__(256)
gemm_hmma(const __nv_bfloat16* __restrict__ A, const __nv_bfloat16* __restrict__ B,
          const float* __restrict__ R, float* __restrict__ out, int Kdim, int Mtotal)
{
    __shared__ __align__(1024) char smem[49152];   // A:2x16KB, B:2x8KB
    const int tid = threadIdx.x;
    const int wid = tid>>5, lane = tid&31;
    const int gid = lane>>2, t4 = lane&3;
    const int b  = blockIdx.z;
    const int m0 = blockIdx.y*128;
    const int n0 = blockIdx.x*64;

    const uint32_t sbase = smem_u32(smem);
    const __nv_bfloat16* Ab = A + (size_t)m0*Kdim;
    const __nv_bfloat16* Bb = B + (size_t)b*Kdim*HWS + n0;

    const int m0w = (wid&3)*32;      // warp m offset (4 warps over 128)
    const int n0w = (wid>>2)*32;     // warp n offset (2 warps over 64)

    float acc[2][4][4] = {};

    const int nch = Kdim >> 6;

    // fill lambda-ish via macro-expanded code
    auto fill = [&](int k0, int st){
        uint32_t aA = sbase + st*16384;
        uint32_t aB = sbase + 32768 + st*8192;
        #pragma unroll
        for (int i=0;i<4;i++){
            int e = tid + i*256;           // 1024 16B chunks for A
            int m = e>>3, c = e&7;
            CP_ASYNC16(aA + SWZ(m*128 + c*16), Ab + (size_t)m*Kdim + k0 + c*8);
        }
        #pragma unroll
        for (int i=0;i<2;i++){
            int e = tid + i*256;           // 512 16B chunks for B
            int k = e>>3, c = e&7;
            CP_ASYNC16(aB + SWZ(k*128 + c*16), Bb + (size_t)(k0+k)*HWS + c*8);
        }
    };

    fill(0, 0);
    CP_COMMIT();

    for (int c=0;c<nch;c++){
        if (c+1 < nch){ fill((c+1)<<6, (c+1)&1); CP_COMMIT(); CP_WAIT1(); }
        else          { CP_WAIT0(); }
        __syncthreads();
        const char* sa = smem + (c&1)*16384;
        const char* sb = smem + 32768 + (c&1)*8192;
        #pragma unroll
        for (int ks=0; ks<4; ks++){
            uint32_t a[2][4];
            #pragma unroll
            for (int mi=0; mi<2; mi++){
                int r  = m0w + mi*16 + gid;
                int o0 = r*128 + ks*32 + t4*4;
                int o1 = (r+8)*128 + ks*32 + t4*4;
                a[mi][0] = *(const uint32_t*)(sa + SWZ(o0));
                a[mi][1] = *(const uint32_t*)(sa + SWZ(o1));
                a[mi][2] = *(const uint32_t*)(sa + SWZ(o0+16));
                a[mi][3] = *(const uint32_t*)(sa + SWZ(o1+16));
            }
            #pragma unroll
            for (int ni=0; ni<4; ni++){
                int n  = n0w + ni*8 + gid;
                int kk = ks*16 + t4*2;
                uint32_t lo0 = *(const unsigned short*)(sb + SWZ(kk*128     + n*2));
                uint32_t hi0 = *(const unsigned short*)(sb + SWZ((kk+1)*128 + n*2));
                uint32_t lo1 = *(const unsigned short*)(sb + SWZ((kk+8)*128 + n*2));
                uint32_t hi1 = *(const unsigned short*)(sb + SWZ((kk+9)*128 + n*2));
                uint32_t b0 = lo0 | (hi0<<16);
                uint32_t b1 = lo1 | (hi1<<16);
                MMA16816(acc[0][ni], a[0], b0, b1);
                MMA16816(acc[1][ni], a[1], b0, b1);
            }
        }
        __syncthreads();
    }

    // epilogue
    #pragma unroll
    for (int mi=0; mi<2; mi++){
        int r = m0 + m0w + mi*16 + gid;
        #pragma unroll
        for (int ni=0; ni<4; ni++){
            int col = n0 + n0w + ni*8 + t4*2;
            size_t o0 = ((size_t)b*Mtotal + r)*HWS + col;
            size_t o1 = ((size_t)b*Mtotal + r + 8)*HWS + col;
            float2 v0 = make_float2(acc[mi][ni][0], acc[mi][ni][1]);
            float2 v1 = make_float2(acc[mi][ni][2], acc[mi][ni][3]);
            if (R){
                float2 r0 = *(const float2*)&R[o0];
                float2 r1 = *(const float2*)&R[o1];
                v0.x += r0.x; v0.y += r0.y;
                v1.x += r1.x; v1.y += r1.y;
            }
            *(float2*)&out[o0] = v0;
            *(float2*)&out[o1] = v1;
        }
    }
}

// ---------------- 4. depthwise 3x3 (SAME) on kv ----------------
__global__ void dw_kernel(const float* __restrict__ Wdw)
{
    int idx = blockIdx.x*256 + threadIdx.x;
    int p  = idx & (HWS-1);
    int bc = idx >> 14;
    int ch = bc & 511;
    int x = p & (WWp-1), y = p >> 7;
    const float* w  = Wdw + ch*9;
    const float* in = g_kv + (size_t)bc*HWS;
    float acc = 0.f;
    for (int dy=-1;dy<=1;dy++){
        int yy=y+dy; if (yy<0||yy>=HH) continue;
        for (int dx=-1;dx<=1;dx++){
            int xx=x+dx; if (xx<0||xx>=WWp) continue;
            acc += __ldg(&w[(dy+1)*3+dx+1]) * in[yy*WWp+xx];
        }
    }
    g_kv2[(size_t)bc*HWS + p] = acc;
}

// ---------------- 5. per-channel L2 norms of q and k ----------------
__global__ void norm_kernel()
{
    int bc = blockIdx.x;
    bool isq = (blockIdx.y==0);
    int b = bc >> 8, c = bc & 255;
    const float* src = isq ? (g_q   + ((size_t)b*CC   + c)*HWS)
                           : (g_kv2 + ((size_t)b*2*CC + c)*HWS);
    float s=0.f;
    for (int i=threadIdx.x; i<HWS; i+=256){ float v=src[i]; s+=v*v; }
    __shared__ float red[8];
    for (int o=16;o>0;o>>=1) s += __shfl_xor_sync(0xffffffffu, s, o);
    if ((threadIdx.x&31)==0) red[threadIdx.x>>5]=s;
    __syncthreads();
    if (threadIdx.x<8){
        float v = red[threadIdx.x];
        for (int o=4;o>0;o>>=1) v += __shfl_xor_sync(0x000000ffu, v, o);
        if (threadIdx.x==0)
            (isq?g_invq:g_invk)[bc] = 1.f / fmaxf(sqrtf(v), 1e-12f);
    }
}

// ---------------- 6. attention scores: split-K QK^T partials ----------------
__global__ void __launch_bounds__(256) attn_part_kernel()
{
    __shared__ float Qs[CHD][65];
    __shared__ float Kt[64][33];
    int bh = blockIdx.y;
    int b = bh >> 3, h = bh & 7;
    int split = blockIdx.x;
    int n0 = split*2048;
    const float* Qb = g_q   + ((size_t)b*CC   + h*CHD)*HWS;
    const float* Kb = g_kv2 + ((size_t)b*2*CC + h*CHD)*HWS;
    int tid = threadIdx.x;
    int i = tid>>3, jq = tid&7;
    float acc[4]={};
    for (int nc=0;nc<2048;nc+=64){
        for (int idx=tid; idx<2048; idx+=256){
            int r = idx>>6, col = idx&63;
            Qs[r][col] = Qb[(size_t)r*HWS + n0+nc+col];
            Kt[col][r] = Kb[(size_t)r*HWS + n0+nc+col];
        }
        __syncthreads();
        #pragma unroll 8
        for (int cc=0;cc<64;cc++){
            float qv = Qs[i][cc];
            #pragma unroll
            for (int jj=0;jj<4;jj++) acc[jj] += qv * Kt[cc][jq*4+jj];
        }
        __syncthreads();
    }
    #pragma unroll
    for (int jj=0;jj<4;jj++)
        g_attn_part[split][bh*CHD*CHD + i*CHD + jq*4+jj] = acc[jj];
}

// ---------------- 7. combine partials, scale, softmax ----------------
__global__ void softmax_kernel(const float* __restrict__ temp)
{
    int bh = blockIdx.x;
    int b = bh>>3, h = bh&7;
    int tid = threadIdx.x;
    int i = tid>>5, j = tid&31;
    float v = 0.f;
    #pragma unroll
    for (int s=0;s<8;s++) v += g_attn_part[s][bh*1024 + i*32 + j];
    v *= g_invq[b*CC + h*CHD + i] * g_invk[b*CC + h*CHD + j] * temp[h];
    float m = v;
    for (int o=16;o>0;o>>=1) m = fmaxf(m, __shfl_xor_sync(0xffffffffu, m, o));
    float e = expf(v - m);
    float s = e;
    for (int o=16;o>0;o>>=1) s += __shfl_xor_sync(0xffffffffu, s, o);
    g_attn[bh*1024 + i*32 + j] = e / s;
}

// ---------------- 8. out = attn @ v  (write bf16 for proj GEMM) ----------------
__global__ void __launch_bounds__(128) av_kernel()
{
    __shared__ float Amat[CHD][CHD];
    int bh = blockIdx.y; int b=bh>>3, h=bh&7;
    int n0 = blockIdx.x*128;
    int tid = threadIdx.x;
    for (int idx=tid; idx<CHD*CHD; idx+=128) ((float*)Amat)[idx] = g_attn[bh*1024+idx];
    __syncthreads();
    const float* Vb = g_kv2 + ((size_t)b*2*CC + CC + h*CHD)*HWS;
    float accv[CHD];
    #pragma unroll
    for (int i=0;i<CHD;i++) accv[i]=0.f;
    int n = n0 + tid;
    #pragma unroll 4
    for (int j=0;j<CHD;j++){
        float vj = Vb[(size_t)j*HWS + n];
        #pragma unroll
        for (int i=0;i<CHD;i++) accv[i] += Amat[i][j]*vj;
    }
    __nv_bfloat16* Ob = g_avb + ((size_t)b*CC + h*CHD)*HWS;
    #pragma unroll
    for (int i=0;i<CHD;i++) Ob[(size_t)i*HWS + n] = __float2bfloat16(accv[i]);
}

// ---------------- launch ----------------
extern "C" void kernel_launch(void* const* d_in, const int* in_sizes, int n_in,
                              void* d_out, int out_size)
{
    const float* x       = (const float*)d_in[0];
    const float* y       = (const float*)d_in[1];
    const float* ln_kv_w = (const float*)d_in[2];
    const float* ln_kv_b = (const float*)d_in[3];
    const float* ln_q_w  = (const float*)d_in[4];
    const float* ln_q_b  = (const float*)d_in[5];
    const float* W_kv    = (const float*)d_in[6];
    const float* W_dw    = (const float*)d_in[7];
    const float* W_q     = (const float*)d_in[8];
    const float* W_proj  = (const float*)d_in[9];
    const float* temp    = (const float*)d_in[10];
    float* out = (float*)d_out;

    __nv_bfloat16 *p_xn, *p_imq, *p_avb, *p_Wkv, *p_Wq, *p_Wp;
    float *p_kv, *p_q, *p_yn;
    cudaGetSymbolAddress((void**)&p_xn,  g_xn);
    cudaGetSymbolAddress((void**)&p_imq, g_imq);
    cudaGetSymbolAddress((void**)&p_avb, g_avb);
    cudaGetSymbolAddress((void**)&p_Wkv, g_Wkv);
    cudaGetSymbolAddress((void**)&p_Wq,  g_Wq);
    cudaGetSymbolAddress((void**)&p_Wp,  g_Wp);
    cudaGetSymbolAddress((void**)&p_kv,  g_kv);
    cudaGetSymbolAddress((void**)&p_q,   g_q);
    cudaGetSymbolAddress((void**)&p_yn,  g_yn);

    convw_kernel<<<3072, 256>>>(W_kv, W_q, W_proj);
    ln_kernel<<<dim3(256,2), 256>>>(x, y, ln_kv_w, ln_kv_b, ln_q_w, ln_q_b);
    shift9_kernel<<<dim3(64, 9*CC, BB), 256>>>();
    // kv = W_kv @ xn   (M=512, K=256)
    gemm_hmma<<<dim3(256, 4, BB), 256>>>(p_Wkv, p_xn, nullptr, p_kv, CC, 2*CC);
    dw_kernel<<<131072, 256>>>(W_dw);
    // q = W_q(3x3) @ yn via im2col  (M=256, K=2304)
    gemm_hmma<<<dim3(256, 2, BB), 256>>>(p_Wq, p_imq, nullptr, p_q, KQ, CC);
    norm_kernel<<<dim3(1024,2), 256>>>();
    attn_part_kernel<<<dim3(8,32), 256>>>();
    softmax_kernel<<<32, 1024>>>(temp);
    av_kernel<<<dim3(128,32), 128>>>();
    // out = yn + W_proj @ av  (M=256, K=256, residual)
    gemm_hmma<<<dim3(256, 2, BB), 256>>>(p_Wp, p_avb, p_yn, out, CC, CC);
}

// round 8
// speedup vs baseline: 4.0131x; 1.6131x over previous
#include <cuda_runtime.h>
#include <cuda_bf16.h>
#include <cstdint>
#include <math.h>

#define BB   4
#define CC   256
#define HH   128
#define WWp  128
#define HWS  16384      // HH*WWp
#define HEADS 8
#define CHD  32         // CC/HEADS
#define KQ   2304       // 9*CC for 3x3 conv as GEMM

// ---------------- scratch (device globals; no allocation) ----------------
__device__ __nv_bfloat16 g_xn [BB*CC*HWS];          // LN(x) in bf16 (kv GEMM B)
__device__ float         g_yn [BB*CC*HWS];          // LN(y) fp32 (residual)
__device__ __nv_bfloat16 g_ynb[BB*CC*HWS];          // LN(y) bf16 (shift9 source)
__device__ __nv_bfloat16 g_imq[(size_t)BB*KQ*HWS];  // 9 shifted copies of yn (q GEMM B)
__device__ float         g_kv [BB*2*CC*HWS];        // kv conv out fp32
__device__ float         g_kv2[BB*2*CC*HWS];        // after depthwise
__device__ float         g_q  [BB*CC*HWS];          // q conv out fp32
__device__ __nv_bfloat16 g_avb[BB*CC*HWS];          // attn@v in bf16 (proj GEMM B)
__device__ float g_invq[BB*CC];
__device__ float g_invk[BB*CC];
__device__ float g_attn_part[8][BB*HEADS*CHD*CHD];
__device__ float g_attn[BB*HEADS*CHD*CHD];
// bf16 weights
__device__ __nv_bfloat16 g_Wkv[2*CC*CC];
__device__ __nv_bfloat16 g_Wq [CC*KQ];
__device__ __nv_bfloat16 g_Wp [CC*CC];

// ---------------- helpers ----------------
__device__ __forceinline__ uint32_t smem_u32(const void* p){
    uint32_t a;
    asm("{ .reg .u64 t; cvta.to.shared.u64 t, %1; cvt.u32.u64 %0, t; }" : "=r"(a) : "l"(p));
    return a;
}
#define SWZ(o) ((o) ^ (((o)>>3)&0x70))
#define CP_ASYNC16(dst, src) \
    asm volatile("cp.async.cg.shared.global [%0], [%1], 16;" :: "r"(dst), "l"(src))
#define CP_COMMIT() asm volatile("cp.async.commit_group;" ::: "memory")
#define CP_WAIT1()  asm volatile("cp.async.wait_group 1;" ::: "memory")
#define CP_WAIT0()  asm volatile("cp.async.wait_group 0;" ::: "memory")
#define MMA16816(c, a, b0, b1) \
    asm volatile("mma.sync.aligned.m16n8k16.row.col.f32.bf16.bf16.f32 " \
        "{%0,%1,%2,%3}, {%4,%5,%6,%7}, {%8,%9}, {%0,%1,%2,%3};" \
        : "+f"((c)[0]), "+f"((c)[1]), "+f"((c)[2]), "+f"((c)[3]) \
        : "r"((a)[0]), "r"((a)[1]), "r"((a)[2]), "r"((a)[3]), "r"(b0), "r"(b1))
#define LDSM_X4(r, addr) \
    asm volatile("ldmatrix.sync.aligned.m8n8.x4.shared.b16 {%0,%1,%2,%3}, [%4];" \
        : "=r"((r)[0]), "=r"((r)[1]), "=r"((r)[2]), "=r"((r)[3]) : "r"(addr))
#define LDSM_X4T(r, addr) \
    asm volatile("ldmatrix.sync.aligned.m8n8.x4.trans.shared.b16 {%0,%1,%2,%3}, [%4];" \
        : "=r"((r)[0]), "=r"((r)[1]), "=r"((r)[2]), "=r"((r)[3]) : "r"(addr))

// ---------------- 0. weight convert / reorder to bf16 ----------------
__global__ void convw_kernel(const float* __restrict__ Wkv, const float* __restrict__ Wq,
                             const float* __restrict__ Wp)
{
    int i = blockIdx.x*256 + threadIdx.x;
    if (i < 2*CC*CC) {                       // W_kv [512][256]
        g_Wkv[i] = __float2bfloat16(Wkv[i]);
    } else if (i < 2*CC*CC + CC*KQ) {        // W_q [256][256][3][3] -> [co][t*256+ci]
        int j = i - 2*CC*CC;
        int co = j / KQ, r = j % KQ;
        int t = r >> 8, ci = r & 255;
        g_Wq[j] = __float2bfloat16(Wq[((size_t)(co*CC+ci))*9 + t]);
    } else if (i < 2*CC*CC + CC*KQ + CC*CC) {
        int j = i - (2*CC*CC + CC*KQ);
        g_Wp[j] = __float2bfloat16(Wp[j]);
    }
}

// ---------------- 1. LayerNorm over channel dim ----------------
__global__ void ln_kernel(const float* __restrict__ x, const float* __restrict__ y,
                          const float* __restrict__ wkv, const float* __restrict__ bkv,
                          const float* __restrict__ wq,  const float* __restrict__ bq)
{
    int idx = blockIdx.x*blockDim.x + threadIdx.x;
    int b = idx >> 14;
    int p = idx & (HWS-1);
    size_t base = (size_t)b*CC*HWS + p;
    if (blockIdx.y == 0) {
        float s=0.f, s2=0.f;
        #pragma unroll 8
        for (int c=0;c<CC;c++){ float v = x[base + (size_t)c*HWS]; s+=v; s2+=v*v; }
        float mu = s*(1.f/CC), var = s2*(1.f/CC)-mu*mu, rs = rsqrtf(var+1e-5f);
        #pragma unroll 8
        for (int c=0;c<CC;c++){
            float v = x[base + (size_t)c*HWS];
            g_xn[base + (size_t)c*HWS] = __float2bfloat16((v-mu)*rs*wkv[c]+bkv[c]);
        }
    } else {
        float s=0.f, s2=0.f;
        #pragma unroll 8
        for (int c=0;c<CC;c++){ float v = y[base + (size_t)c*HWS]; s+=v; s2+=v*v; }
        float mu = s*(1.f/CC), var = s2*(1.f/CC)-mu*mu, rs = rsqrtf(var+1e-5f);
        #pragma unroll 8
        for (int c=0;c<CC;c++){
            float v = y[base + (size_t)c*HWS];
            float r = (v-mu)*rs*wq[c]+bq[c];
            g_yn [base + (size_t)c*HWS] = r;
            g_ynb[base + (size_t)c*HWS] = __float2bfloat16(r);
        }
    }
}

// ---------------- 2. build 9 shifted bf16 copies of yn (im2col) ----------------
__global__ void shift9_kernel()
{
    int p  = blockIdx.x*256 + threadIdx.x;        // pixel
    int t  = blockIdx.y >> 8;                     // tap 0..8 (kh*3+kw)
    int ci = blockIdx.y & 255;
    int b  = blockIdx.z;
    int yy = (p >> 7) + (t/3) - 1;
    int xx = (p & 127) + (t%3) - 1;
    __nv_bfloat16 v = __float2bfloat16(0.f);
    if (yy>=0 && yy<HH && xx>=0 && xx<WWp)
        v = g_ynb[(((size_t)b*CC + ci)<<14) + (yy<<7) + xx];
    g_imq[(((size_t)b*KQ + t*CC + ci)<<14) + p] = v;
}

// ---------------- 3. HMMA bf16 GEMM: out[b,m,n] = sum_k A[m,k]*B[b,k,n] (+R) ------
// CTA tile: M=128, N=64, K chunk 64, double-buffered cp.async, 8 warps of 32x32.
// A smem: [128 m][64 k] bf16, 128B rows, SW128 swizzle.
// B smem: [64 k][64 n] bf16, 128B rows, SW128 swizzle.
__global__ void __launch_bounds__(256, 2)
gemm_hmma(const __nv_bfloat16* __restrict__ A, const __nv_bfloat16* __restrict__ B,
          const float* __restrict__ R, float* __restrict__ out, int Kdim, int Mtotal)
{
    __shared__ __align__(1024) char smem[49152];   // A:2x16KB, B:2x8KB
    const int tid = threadIdx.x;
    const int wid = tid>>5, lane = tid&31;
    const int gid = lane>>2, t4 = lane&3;
    const int b  = blockIdx.z;
    const int m0 = blockIdx.y*128;
    const int n0 = blockIdx.x*64;

    const uint32_t sbase = smem_u32(smem);
    const __nv_bfloat16* Ab = A + (size_t)m0*Kdim;
    const __nv_bfloat16* Bb = B + (size_t)b*Kdim*HWS + n0;

    const int m0w = (wid&3)*32;      // warp m offset (4 warps over 128)
    const int n0w = (wid>>2)*32;     // warp n offset (2 warps over 64)

    // ldmatrix per-thread base offsets (within a stage)
    const int l16 = lane & 15, lhi = (lane >> 4) * 16;
    uint32_t baseA0 = (uint32_t)((m0w +      l16)*128 + lhi);
    uint32_t baseA1 = (uint32_t)((m0w + 16 + l16)*128 + lhi);
    uint32_t baseB0 = (uint32_t)(l16*128 + (n0w     )*2 + lhi);
    uint32_t baseB1 = (uint32_t)(l16*128 + (n0w + 16)*2 + lhi);

    float acc[2][4][4] = {};

    const int nch = Kdim >> 6;

    auto fill = [&](int k0, int st){
        uint32_t aA = sbase + st*16384;
        uint32_t aB = sbase + 32768 + st*8192;
        #pragma unroll
        for (int i=0;i<4;i++){
            int e = tid + i*256;           // 1024 16B chunks for A
            int m = e>>3, c = e&7;
            CP_ASYNC16(aA + SWZ(m*128 + c*16), Ab + (size_t)m*Kdim + k0 + c*8);
        }
        #pragma unroll
        for (int i=0;i<2;i++){
            int e = tid + i*256;           // 512 16B chunks for B
            int k = e>>3, c = e&7;
            CP_ASYNC16(aB + SWZ(k*128 + c*16), Bb + (size_t)(k0+k)*HWS + c*8);
        }
    };

    fill(0, 0);
    CP_COMMIT();

    for (int c=0;c<nch;c++){
        if (c+1 < nch){ fill((c+1)<<6, (c+1)&1); CP_COMMIT(); CP_WAIT1(); }
        else          { CP_WAIT0(); }
        __syncthreads();
        const uint32_t aA = sbase + (c&1)*16384;
        const uint32_t aB = sbase + 32768 + (c&1)*8192;
        #pragma unroll
        for (int ks=0; ks<4; ks++){
            uint32_t af0[4], af1[4], bf0[4], bf1[4];
            LDSM_X4 (af0, aA + SWZ(baseA0 + ks*32));
            LDSM_X4 (af1, aA + SWZ(baseA1 + ks*32));
            LDSM_X4T(bf0, aB + SWZ(baseB0 + ks*2048));
            LDSM_X4T(bf1, aB + SWZ(baseB1 + ks*2048));
            MMA16816(acc[0][0], af0, bf0[0], bf0[1]);
            MMA16816(acc[0][1], af0, bf0[2], bf0[3]);
            MMA16816(acc[0][2], af0, bf1[0], bf1[1]);
            MMA16816(acc[0][3], af0, bf1[2], bf1[3]);
            MMA16816(acc[1][0], af1, bf0[0], bf0[1]);
            MMA16816(acc[1][1], af1, bf0[2], bf0[3]);
            MMA16816(acc[1][2], af1, bf1[0], bf1[1]);
            MMA16816(acc[1][3], af1, bf1[2], bf1[3]);
        }
        __syncthreads();
    }

    // epilogue
    #pragma unroll
    for (int mi=0; mi<2; mi++){
        int r = m0 + m0w + mi*16 + gid;
        #pragma unroll
        for (int ni=0; ni<4; ni++){
            int col = n0 + n0w + ni*8 + t4*2;
            size_t o0 = ((size_t)b*Mtotal + r)*HWS + col;
            size_t o1 = ((size_t)b*Mtotal + r + 8)*HWS + col;
            float2 v0 = make_float2(acc[mi][ni][0], acc[mi][ni][1]);
            float2 v1 = make_float2(acc[mi][ni][2], acc[mi][ni][3]);
            if (R){
                float2 r0 = *(const float2*)&R[o0];
                float2 r1 = *(const float2*)&R[o1];
                v0.x += r0.x; v0.y += r0.y;
                v1.x += r1.x; v1.y += r1.y;
            }
            *(float2*)&out[o0] = v0;
            *(float2*)&out[o1] = v1;
        }
    }
}

// ---------------- 4. depthwise 3x3 (SAME) on kv ----------------
__global__ void dw_kernel(const float* __restrict__ Wdw)
{
    int idx = blockIdx.x*256 + threadIdx.x;
    int p  = idx & (HWS-1);
    int bc = idx >> 14;
    int ch = bc & 511;
    int x = p & (WWp-1), y = p >> 7;
    const float* w  = Wdw + ch*9;
    const float* in = g_kv + (size_t)bc*HWS;
    float acc = 0.f;
    for (int dy=-1;dy<=1;dy++){
        int yy=y+dy; if (yy<0||yy>=HH) continue;
        for (int dx=-1;dx<=1;dx++){
            int xx=x+dx; if (xx<0||xx>=WWp) continue;
            acc += __ldg(&w[(dy+1)*3+dx+1]) * in[yy*WWp+xx];
        }
    }
    g_kv2[(size_t)bc*HWS + p] = acc;
}

// ---------------- 5. per-channel L2 norms of q and k ----------------
__global__ void norm_kernel()
{
    int bc = blockIdx.x;
    bool isq = (blockIdx.y==0);
    int b = bc >> 8, c = bc & 255;
    const float* src = isq ? (g_q   + ((size_t)b*CC   + c)*HWS)
                           : (g_kv2 + ((size_t)b*2*CC + c)*HWS);
    float s=0.f;
    for (int i=threadIdx.x; i<HWS; i+=256){ float v=src[i]; s+=v*v; }
    __shared__ float red[8];
    for (int o=16;o>0;o>>=1) s += __shfl_xor_sync(0xffffffffu, s, o);
    if ((threadIdx.x&31)==0) red[threadIdx.x>>5]=s;
    __syncthreads();
    if (threadIdx.x<8){
        float v = red[threadIdx.x];
        for (int o=4;o>0;o>>=1) v += __shfl_xor_sync(0x000000ffu, v, o);
        if (threadIdx.x==0)
            (isq?g_invq:g_invk)[bc] = 1.f / fmaxf(sqrtf(v), 1e-12f);
    }
}

// ---------------- 6. attention scores: split-K QK^T partials ----------------
__global__ void __launch_bounds__(256) attn_part_kernel()
{
    __shared__ float Qs[CHD][65];
    __shared__ float Kt[64][33];
    int bh = blockIdx.y;
    int b = bh >> 3, h = bh & 7;
    int split = blockIdx.x;
    int n0 = split*2048;
    const float* Qb = g_q   + ((size_t)b*CC   + h*CHD)*HWS;
    const float* Kb = g_kv2 + ((size_t)b*2*CC + h*CHD)*HWS;
    int tid = threadIdx.x;
    int i = tid>>3, jq = tid&7;
    float acc[4]={};
    for (int nc=0;nc<2048;nc+=64){
        for (int idx=tid; idx<2048; idx+=256){
            int r = idx>>6, col = idx&63;
            Qs[r][col] = Qb[(size_t)r*HWS + n0+nc+col];
            Kt[col][r] = Kb[(size_t)r*HWS + n0+nc+col];
        }
        __syncthreads();
        #pragma unroll 8
        for (int cc=0;cc<64;cc++){
            float qv = Qs[i][cc];
            #pragma unroll
            for (int jj=0;jj<4;jj++) acc[jj] += qv * Kt[cc][jq*4+jj];
        }
        __syncthreads();
    }
    #pragma unroll
    for (int jj=0;jj<4;jj++)
        g_attn_part[split][bh*CHD*CHD + i*CHD + jq*4+jj] = acc[jj];
}

// ---------------- 7. combine partials, scale, softmax ----------------
__global__ void softmax_kernel(const float* __restrict__ temp)
{
    int bh = blockIdx.x;
    int b = bh>>3, h = bh&7;
    int tid = threadIdx.x;
    int i = tid>>5, j = tid&31;
    float v = 0.f;
    #pragma unroll
    for (int s=0;s<8;s++) v += g_attn_part[s][bh*1024 + i*32 + j];
    v *= g_invq[b*CC + h*CHD + i] * g_invk[b*CC + h*CHD + j] * temp[h];
    float m = v;
    for (int o=16;o>0;o>>=1) m = fmaxf(m, __shfl_xor_sync(0xffffffffu, m, o));
    float e = expf(v - m);
    float s = e;
    for (int o=16;o>0;o>>=1) s += __shfl_xor_sync(0xffffffffu, s, o);
    g_attn[bh*1024 + i*32 + j] = e / s;
}

// ---------------- 8. out = attn @ v  (write bf16 for proj GEMM) ----------------
__global__ void __launch_bounds__(128) av_kernel()
{
    __shared__ float Amat[CHD][CHD];
    int bh = blockIdx.y; int b=bh>>3, h=bh&7;
    int n0 = blockIdx.x*128;
    int tid = threadIdx.x;
    for (int idx=tid; idx<CHD*CHD; idx+=128) ((float*)Amat)[idx] = g_attn[bh*1024+idx];
    __syncthreads();
    const float* Vb = g_kv2 + ((size_t)b*2*CC + CC + h*CHD)*HWS;
    float accv[CHD];
    #pragma unroll
    for (int i=0;i<CHD;i++) accv[i]=0.f;
    int n = n0 + tid;
    #pragma unroll 4
    for (int j=0;j<CHD;j++){
        float vj = Vb[(size_t)j*HWS + n];
        #pragma unroll
        for (int i=0;i<CHD;i++) accv[i] += Amat[i][j]*vj;
    }
    __nv_bfloat16* Ob = g_avb + ((size_t)b*CC + h*CHD)*HWS;
    #pragma unroll
    for (int i=0;i<CHD;i++) Ob[(size_t)i*HWS + n] = __float2bfloat16(accv[i]);
}

// ---------------- launch ----------------
extern "C" void kernel_launch(void* const* d_in, const int* in_sizes, int n_in,
                              void* d_out, int out_size)
{
    const float* x       = (const float*)d_in[0];
    const float* y       = (const float*)d_in[1];
    const float* ln_kv_w = (const float*)d_in[2];
    const float* ln_kv_b = (const float*)d_in[3];
    const float* ln_q_w  = (const float*)d_in[4];
    const float* ln_q_b  = (const float*)d_in[5];
    const float* W_kv    = (const float*)d_in[6];
    const float* W_dw    = (const float*)d_in[7];
    const float* W_q     = (const float*)d_in[8];
    const float* W_proj  = (const float*)d_in[9];
    const float* temp    = (const float*)d_in[10];
    float* out = (float*)d_out;

    __nv_bfloat16 *p_xn, *p_imq, *p_avb, *p_Wkv, *p_Wq, *p_Wp;
    float *p_kv, *p_q, *p_yn;
    cudaGetSymbolAddress((void**)&p_xn,  g_xn);
    cudaGetSymbolAddress((void**)&p_imq, g_imq);
    cudaGetSymbolAddress((void**)&p_avb, g_avb);
    cudaGetSymbolAddress((void**)&p_Wkv, g_Wkv);
    cudaGetSymbolAddress((void**)&p_Wq,  g_Wq);
    cudaGetSymbolAddress((void**)&p_Wp,  g_Wp);
    cudaGetSymbolAddress((void**)&p_kv,  g_kv);
    cudaGetSymbolAddress((void**)&p_q,   g_q);
    cudaGetSymbolAddress((void**)&p_yn,  g_yn);

    convw_kernel<<<3072, 256>>>(W_kv, W_q, W_proj);
    ln_kernel<<<dim3(256,2), 256>>>(x, y, ln_kv_w, ln_kv_b, ln_q_w, ln_q_b);
    shift9_kernel<<<dim3(64, 9*CC, BB), 256>>>();
    // kv = W_kv @ xn   (M=512, K=256)
    gemm_hmma<<<dim3(256, 4, BB), 256>>>(p_Wkv, p_xn, nullptr, p_kv, CC, 2*CC);
    dw_kernel<<<131072, 256>>>(W_dw);
    // q = W_q(3x3) @ yn via im2col  (M=256, K=2304)
    gemm_hmma<<<dim3(256, 2, BB), 256>>>(p_Wq, p_imq, nullptr, p_q, KQ, CC);
    norm_kernel<<<dim3(1024,2), 256>>>();
    attn_part_kernel<<<dim3(8,32), 256>>>();
    softmax_kernel<<<32, 1024>>>(temp);
    av_kernel<<<dim3(128,32), 128>>>();
    // out = yn + W_proj @ av  (M=256, K=256, residual)
    gemm_hmma<<<dim3(256, 2, BB), 256>>>(p_Wp, p_avb, p_yn, out, CC, CC);
}

// round 9
// speedup vs baseline: 5.3727x; 1.3388x over previous
#include <cuda_runtime.h>
#include <cuda_bf16.h>
#include <cstdint>
#include <math.h>

#define BB   4
#define CC   256
#define HH   128
#define WWp  128
#define HWS  16384      // HH*WWp
#define HEADS 8
#define CHD  32         // CC/HEADS
#define KQ   2304       // 9*CC for 3x3 conv as GEMM

// ---------------- scratch (device globals; no allocation) ----------------
__device__ __nv_bfloat16 g_xn  [BB*CC*HWS];          // LN(x) bf16 (kv GEMM B)
__device__ float         g_yn  [BB*CC*HWS];          // LN(y) fp32 (residual)
__device__ __nv_bfloat16 g_ynb [BB*CC*HWS];          // LN(y) bf16 (im2col source)
__device__ __nv_bfloat16 g_imq [(size_t)BB*KQ*HWS];  // im2col of yn (q GEMM B)
__device__ __nv_bfloat16 g_kvb [BB*2*CC*HWS];        // kv conv out bf16
__device__ __nv_bfloat16 g_kv2b[BB*2*CC*HWS];        // after depthwise, bf16
__device__ __nv_bfloat16 g_qb  [BB*CC*HWS];          // q conv out bf16
__device__ __nv_bfloat16 g_avb [BB*CC*HWS];          // attn@v bf16 (proj GEMM B)
__device__ float g_sumq[BB*CC];
__device__ float g_sumk[BB*CC];
__device__ float g_attn_part[8][BB*HEADS*CHD*CHD];
__device__ float g_attn[BB*HEADS*CHD*CHD];
// bf16 weights
__device__ __nv_bfloat16 g_Wkv[2*CC*CC];
__device__ __nv_bfloat16 g_Wq [CC*KQ];
__device__ __nv_bfloat16 g_Wp [CC*CC];

// ---------------- helpers ----------------
__device__ __forceinline__ uint32_t smem_u32(const void* p){
    uint32_t a;
    asm("{ .reg .u64 t; cvta.to.shared.u64 t, %1; cvt.u32.u64 %0, t; }" : "=r"(a) : "l"(p));
    return a;
}
#define SWZ(o) ((o) ^ (((o)>>3)&0x70))
#define CP_ASYNC16(dst, src) \
    asm volatile("cp.async.cg.shared.global [%0], [%1], 16;" :: "r"(dst), "l"(src))
#define CP_COMMIT() asm volatile("cp.async.commit_group;" ::: "memory")
#define CP_WAIT1()  asm volatile("cp.async.wait_group 1;" ::: "memory")
#define CP_WAIT0()  asm volatile("cp.async.wait_group 0;" ::: "memory")
#define MMA16816(c, a, b0, b1) \
    asm volatile("mma.sync.aligned.m16n8k16.row.col.f32.bf16.bf16.f32 " \
        "{%0,%1,%2,%3}, {%4,%5,%6,%7}, {%8,%9}, {%0,%1,%2,%3};" \
        : "+f"((c)[0]), "+f"((c)[1]), "+f"((c)[2]), "+f"((c)[3]) \
        : "r"((a)[0]), "r"((a)[1]), "r"((a)[2]), "r"((a)[3]), "r"(b0), "r"(b1))
#define LDSM_X4(r, addr) \
    asm volatile("ldmatrix.sync.aligned.m8n8.x4.shared.b16 {%0,%1,%2,%3}, [%4];" \
        : "=r"((r)[0]), "=r"((r)[1]), "=r"((r)[2]), "=r"((r)[3]) : "r"(addr))
#define LDSM_X4T(r, addr) \
    asm volatile("ldmatrix.sync.aligned.m8n8.x4.trans.shared.b16 {%0,%1,%2,%3}, [%4];" \
        : "=r"((r)[0]), "=r"((r)[1]), "=r"((r)[2]), "=r"((r)[3]) : "r"(addr))

// ---------------- 0. weight convert + zero norm accumulators ----------------
__global__ void convw_kernel(const float* __restrict__ Wkv, const float* __restrict__ Wq,
                             const float* __restrict__ Wp)
{
    int i = blockIdx.x*256 + threadIdx.x;
    if (i < 2*CC*CC) {                       // W_kv [512][256]
        g_Wkv[i] = __float2bfloat16(Wkv[i]);
    } else if (i < 2*CC*CC + CC*KQ) {        // W_q [256][256][3][3] -> [co][t*256+ci]
        int j = i - 2*CC*CC;
        int co = j / KQ, r = j % KQ;
        int t = r >> 8, ci = r & 255;
        g_Wq[j] = __float2bfloat16(Wq[((size_t)(co*CC+ci))*9 + t]);
    } else if (i < 2*CC*CC + CC*KQ + CC*CC) {
        int j = i - (2*CC*CC + CC*KQ);
        g_Wp[j] = __float2bfloat16(Wp[j]);
    } else {
        int j = i - (2*CC*CC + CC*KQ + CC*CC);
        if (j < BB*CC) g_sumq[j] = 0.f;
        else if (j < 2*BB*CC) g_sumk[j - BB*CC] = 0.f;
    }
}

// ---------------- 1. LayerNorm over channel dim ----------------
__global__ void ln_kernel(const float* __restrict__ x, const float* __restrict__ y,
                          const float* __restrict__ wkv, const float* __restrict__ bkv,
                          const float* __restrict__ wq,  const float* __restrict__ bq)
{
    int idx = blockIdx.x*blockDim.x + threadIdx.x;
    int b = idx >> 14;
    int p = idx & (HWS-1);
    size_t base = (size_t)b*CC*HWS + p;
    if (blockIdx.y == 0) {
        float s=0.f, s2=0.f;
        #pragma unroll 8
        for (int c=0;c<CC;c++){ float v = x[base + (size_t)c*HWS]; s+=v; s2+=v*v; }
        float mu = s*(1.f/CC), var = s2*(1.f/CC)-mu*mu, rs = rsqrtf(var+1e-5f);
        #pragma unroll 8
        for (int c=0;c<CC;c++){
            float v = x[base + (size_t)c*HWS];
            g_xn[base + (size_t)c*HWS] = __float2bfloat16((v-mu)*rs*wkv[c]+bkv[c]);
        }
    } else {
        float s=0.f, s2=0.f;
        #pragma unroll 8
        for (int c=0;c<CC;c++){ float v = y[base + (size_t)c*HWS]; s+=v; s2+=v*v; }
        float mu = s*(1.f/CC), var = s2*(1.f/CC)-mu*mu, rs = rsqrtf(var+1e-5f);
        #pragma unroll 8
        for (int c=0;c<CC;c++){
            float v = y[base + (size_t)c*HWS];
            float r = (v-mu)*rs*wq[c]+bq[c];
            g_yn [base + (size_t)c*HWS] = r;
            g_ynb[base + (size_t)c*HWS] = __float2bfloat16(r);
        }
    }
}

// ---------------- 2. im2col: 9 shifted bf16 copies of yn, 8 px/thread ----------------
__global__ void __launch_bounds__(256) shift9_kernel()
{
    int bx = blockIdx.x;                 // 0..71: tap*8 + seg
    int t = bx>>3, seg = bx&7;
    int ci = blockIdx.y, b = blockIdx.z;
    int tid = threadIdx.x;
    int px0 = seg*2048 + tid*8;
    int y = px0>>7, x0 = px0&127;
    int dy = t/3 - 1, dx = t%3 - 1;
    int yy = y + dy;
    const __nv_bfloat16* src = g_ynb + (((size_t)b*CC + ci)<<14);
    __nv_bfloat16 hv[8];
    if (yy>=0 && yy<HH){
        #pragma unroll
        for (int j=0;j<8;j++){
            int xx = x0 + j + dx;
            hv[j] = (xx>=0 && xx<WWp) ? src[yy*WWp+xx] : __float2bfloat16(0.f);
        }
    } else {
        #pragma unroll
        for (int j=0;j<8;j++) hv[j] = __float2bfloat16(0.f);
    }
    *(uint4*)(g_imq + (((size_t)b*KQ + t*CC + ci)<<14) + px0) = *(uint4*)hv;
}

// ---------------- 3. HMMA bf16 GEMM: out[b,m,n] = sum_k A[m,k]*B[b,k,n] -------------
// CTA tile M=128, N=64, K chunk 128 (2 halves of 64), double-buffered cp.async.
// Dynamic smem 96KB: A 2x32KB (each: 2 halves of 128x64), B 2x16KB (2 halves of 64x64).
// grid = (m_blocks, 256 n_blocks, BB): consecutive CTAs share B tile (L2 reuse).
template<bool OUTBF, bool SUMQ>
__global__ void __launch_bounds__(256, 2)
gemm_hmma(const __nv_bfloat16* __restrict__ A, const __nv_bfloat16* __restrict__ B,
          const float* __restrict__ R, void* __restrict__ outp,
          float* __restrict__ sumsq, int Kdim, int Mtotal)
{
    extern __shared__ __align__(1024) char smem[];
    const int tid = threadIdx.x;
    const int wid = tid>>5, lane = tid&31;
    const int gid = lane>>2, t4 = lane&3;
    const int b  = blockIdx.z;
    const int m0 = blockIdx.x*128;
    const int n0 = blockIdx.y*64;

    const uint32_t sbase = smem_u32(smem);
    const __nv_bfloat16* Ab = A + (size_t)m0*Kdim;
    const __nv_bfloat16* Bb = B + (size_t)b*Kdim*HWS + n0;

    const int m0w = (wid&3)*32;      // warp m offset
    const int n0w = (wid>>2)*32;     // warp n offset

    const int l16 = lane & 15, lhi = (lane >> 4) * 16;
    const uint32_t baseA0 = (uint32_t)((m0w +      l16)*128 + lhi);
    const uint32_t baseA1 = (uint32_t)((m0w + 16 + l16)*128 + lhi);
    const uint32_t baseB0 = (uint32_t)(l16*128 + (n0w     )*2 + lhi);
    const uint32_t baseB1 = (uint32_t)(l16*128 + (n0w + 16)*2 + lhi);

    float acc[2][4][4] = {};
    const int nch = Kdim >> 7;       // K chunks of 128

    auto fill = [&](int k0, int st){
        uint32_t aA = sbase + st*32768;
        uint32_t aB = sbase + 65536 + st*16384;
        #pragma unroll
        for (int i=0;i<8;i++){       // A: 2048 16B chunks
            int e = tid + i*256;
            int m = e>>4, c = e&15, half = c>>3, c8 = c&7;
            CP_ASYNC16(aA + half*16384 + SWZ(m*128 + c8*16),
                       Ab + (size_t)m*Kdim + k0 + half*64 + c8*8);
        }
        #pragma unroll
        for (int i=0;i<4;i++){       // B: 1024 16B chunks
            int e = tid + i*256;
            int k = e>>3, c = e&7, half = k>>6, kr = k&63;
            CP_ASYNC16(aB + half*8192 + SWZ(kr*128 + c*16),
                       Bb + (size_t)(k0+k)*HWS + c*8);
        }
    };

    fill(0, 0);
    CP_COMMIT();

    for (int c=0;c<nch;c++){
        if (c+1 < nch){ fill((c+1)<<7, (c+1)&1); CP_COMMIT(); CP_WAIT1(); }
        else          { CP_WAIT0(); }
        __syncthreads();
        const uint32_t aA = sbase + (c&1)*32768;
        const uint32_t aB = sbase + 65536 + (c&1)*16384;
        #pragma unroll
        for (int half=0; half<2; half++){
            const uint32_t hA = aA + half*16384;
            const uint32_t hB = aB + half*8192;
            #pragma unroll
            for (int ks=0; ks<4; ks++){
                uint32_t af0[4], af1[4], bf0[4], bf1[4];
                LDSM_X4 (af0, hA + SWZ(baseA0 + ks*32));
                LDSM_X4 (af1, hA + SWZ(baseA1 + ks*32));
                LDSM_X4T(bf0, hB + SWZ(baseB0 + ks*2048));
                LDSM_X4T(bf1, hB + SWZ(baseB1 + ks*2048));
                MMA16816(acc[0][0], af0, bf0[0], bf0[1]);
                MMA16816(acc[0][1], af0, bf0[2], bf0[3]);
                MMA16816(acc[0][2], af0, bf1[0], bf1[1]);
                MMA16816(acc[0][3], af0, bf1[2], bf1[3]);
                MMA16816(acc[1][0], af1, bf0[0], bf0[1]);
                MMA16816(acc[1][1], af1, bf0[2], bf0[3]);
                MMA16816(acc[1][2], af1, bf1[0], bf1[1]);
                MMA16816(acc[1][3], af1, bf1[2], bf1[3]);
            }
        }
        __syncthreads();
    }

    // epilogue
    #pragma unroll
    for (int mi=0; mi<2; mi++){
        int r = m0 + m0w + mi*16 + gid;
        #pragma unroll
        for (int ni=0; ni<4; ni++){
            int col = n0 + n0w + ni*8 + t4*2;
            size_t o0 = ((size_t)b*Mtotal + r)*HWS + col;
            size_t o1 = ((size_t)b*Mtotal + r + 8)*HWS + col;
            if (OUTBF){
                __nv_bfloat16* ob = (__nv_bfloat16*)outp;
                __nv_bfloat162 p0, p1;
                p0.x = __float2bfloat16(acc[mi][ni][0]);
                p0.y = __float2bfloat16(acc[mi][ni][1]);
                p1.x = __float2bfloat16(acc[mi][ni][2]);
                p1.y = __float2bfloat16(acc[mi][ni][3]);
                *(__nv_bfloat162*)&ob[o0] = p0;
                *(__nv_bfloat162*)&ob[o1] = p1;
            } else {
                float* of = (float*)outp;
                float2 v0 = make_float2(acc[mi][ni][0], acc[mi][ni][1]);
                float2 v1 = make_float2(acc[mi][ni][2], acc[mi][ni][3]);
                if (R){
                    float2 r0 = *(const float2*)&R[o0];
                    float2 r1 = *(const float2*)&R[o1];
                    v0.x += r0.x; v0.y += r0.y;
                    v1.x += r1.x; v1.y += r1.y;
                }
                *(float2*)&of[o0] = v0;
                *(float2*)&of[o1] = v1;
            }
        }
        if (SUMQ){
            float s0 = 0.f, s1 = 0.f;
            #pragma unroll
            for (int ni=0; ni<4; ni++){
                s0 += acc[mi][ni][0]*acc[mi][ni][0] + acc[mi][ni][1]*acc[mi][ni][1];
                s1 += acc[mi][ni][2]*acc[mi][ni][2] + acc[mi][ni][3]*acc[mi][ni][3];
            }
            s0 += __shfl_xor_sync(0xffffffffu, s0, 1);
            s0 += __shfl_xor_sync(0xffffffffu, s0, 2);
            s1 += __shfl_xor_sync(0xffffffffu, s1, 1);
            s1 += __shfl_xor_sync(0xffffffffu, s1, 2);
            if (t4==0){
                int rr = m0 + m0w + mi*16 + gid;
                atomicAdd(&sumsq[b*CC + rr], s0);
                atomicAdd(&sumsq[b*CC + rr + 8], s1);
            }
        }
    }
}

// ---------------- 4. depthwise 3x3 bf16, 8 px/thread, fused k-norm sums ----------------
__global__ void __launch_bounds__(256) dw_kernel(const float* __restrict__ Wdw)
{
    int bx = blockIdx.x;                 // 0..16383: bc*8 + seg
    int bc = bx>>3, seg = bx&7;
    int b = bc>>9, ch = bc&511;
    int tid = threadIdx.x;
    int px0 = seg*2048 + tid*8;
    int y = px0>>7, x0 = px0&127;
    const __nv_bfloat16* in = g_kvb + (size_t)bc*HWS;
    float w[9];
    #pragma unroll
    for (int i=0;i<9;i++) w[i] = __ldg(&Wdw[ch*9+i]);
    float buf[3][12];
    #pragma unroll
    for (int r=0;r<3;r++){
        int yy = y + r - 1;
        bool rowok = (yy>=0 && yy<HH);
        #pragma unroll
        for (int j=0;j<6;j++){
            int cx = x0 - 2 + 2*j;
            float vx = 0.f, vy = 0.f;
            if (rowok && cx>=0 && cx<WWp){
                __nv_bfloat162 t = *(const __nv_bfloat162*)(in + yy*WWp + cx);
                vx = __bfloat162float(t.x); vy = __bfloat162float(t.y);
            }
            buf[r][2*j] = vx; buf[r][2*j+1] = vy;
        }
    }
    __nv_bfloat16 hv[8];
    float s = 0.f;
    #pragma unroll
    for (int j=0;j<8;j++){
        float acc = 0.f;
        #pragma unroll
        for (int r=0;r<3;r++)
            #pragma unroll
            for (int d=0;d<3;d++)
                acc += w[r*3+d]*buf[r][j+1+d];
        hv[j] = __float2bfloat16(acc);
        float f = __bfloat162float(hv[j]);
        s += f*f;
    }
    *(uint4*)(g_kv2b + (size_t)bc*HWS + px0) = *(uint4*)hv;
    if (ch < 256){
        for (int o=16;o>0;o>>=1) s += __shfl_xor_sync(0xffffffffu, s, o);
        __shared__ float red[8];
        if ((tid&31)==0) red[tid>>5]=s;
        __syncthreads();
        if (tid<8){
            float v2 = red[tid];
            for (int o=4;o>0;o>>=1) v2 += __shfl_xor_sync(0x000000ffu, v2, o);
            if (tid==0) atomicAdd(&g_sumk[b*CC+ch], v2);
        }
    }
}

// ---------------- 6. attention scores: split-K QK^T partials (bf16 in) ----------------
__global__ void __launch_bounds__(256) attn_part_kernel()
{
    __shared__ float Qs[CHD][65];
    __shared__ float Kt[64][33];
    int bh = blockIdx.y;
    int b = bh >> 3, h = bh & 7;
    int split = blockIdx.x;
    int n0 = split*2048;
    const __nv_bfloat16* Qb = g_qb   + ((size_t)b*CC   + h*CHD)*HWS;
    const __nv_bfloat16* Kb = g_kv2b + ((size_t)b*2*CC + h*CHD)*HWS;
    int tid = threadIdx.x;
    int i = tid>>3, jq = tid&7;
    float acc[4]={};
    for (int nc=0;nc<2048;nc+=64){
        for (int idx=tid; idx<2048; idx+=256){
            int r = idx>>6, col = idx&63;
            Qs[r][col] = __bfloat162float(Qb[(size_t)r*HWS + n0+nc+col]);
            Kt[col][r] = __bfloat162float(Kb[(size_t)r*HWS + n0+nc+col]);
        }
        __syncthreads();
        #pragma unroll 8
        for (int cc=0;cc<64;cc++){
            float qv = Qs[i][cc];
            #pragma unroll
            for (int jj=0;jj<4;jj++) acc[jj] += qv * Kt[cc][jq*4+jj];
        }
        __syncthreads();
    }
    #pragma unroll
    for (int jj=0;jj<4;jj++)
        g_attn_part[split][bh*CHD*CHD + i*CHD + jq*4+jj] = acc[jj];
}

// ---------------- 7. combine partials, normalize, scale, softmax ----------------
__global__ void softmax_kernel(const float* __restrict__ temp)
{
    int bh = blockIdx.x;
    int b = bh>>3, h = bh&7;
    int tid = threadIdx.x;
    int i = tid>>5, j = tid&31;
    float v = 0.f;
    #pragma unroll
    for (int s=0;s<8;s++) v += g_attn_part[s][bh*1024 + i*32 + j];
    float iq = 1.f / fmaxf(sqrtf(g_sumq[b*CC + h*CHD + i]), 1e-12f);
    float ik = 1.f / fmaxf(sqrtf(g_sumk[b*CC + h*CHD + j]), 1e-12f);
    v *= iq * ik * temp[h];
    float m = v;
    for (int o=16;o>0;o>>=1) m = fmaxf(m, __shfl_xor_sync(0xffffffffu, m, o));
    float e = expf(v - m);
    float s = e;
    for (int o=16;o>0;o>>=1) s += __shfl_xor_sync(0xffffffffu, s, o);
    g_attn[bh*1024 + i*32 + j] = e / s;
}

// ---------------- 8. out = attn @ v  (bf16 in/out) ----------------
__global__ void __launch_bounds__(128) av_kernel()
{
    __shared__ float Amat[CHD][CHD];
    int bh = blockIdx.y; int b=bh>>3, h=bh&7;
    int n0 = blockIdx.x*128;
    int tid = threadIdx.x;
    for (int idx=tid; idx<CHD*CHD; idx+=128) ((float*)Amat)[idx] = g_attn[bh*1024+idx];
    __syncthreads();
    const __nv_bfloat16* Vb = g_kv2b + ((size_t)b*2*CC + CC + h*CHD)*HWS;
    float accv[CHD];
    #pragma unroll
    for (int i=0;i<CHD;i++) accv[i]=0.f;
    int n = n0 + tid;
    #pragma unroll 4
    for (int j=0;j<CHD;j++){
        float vj = __bfloat162float(Vb[(size_t)j*HWS + n]);
        #pragma unroll
        for (int i=0;i<CHD;i++) accv[i] += Amat[i][j]*vj;
    }
    __nv_bfloat16* Ob = g_avb + ((size_t)b*CC + h*CHD)*HWS;
    #pragma unroll
    for (int i=0;i<CHD;i++) Ob[(size_t)i*HWS + n] = __float2bfloat16(accv[i]);
}

// ---------------- launch ----------------
extern "C" void kernel_launch(void* const* d_in, const int* in_sizes, int n_in,
                              void* d_out, int out_size)
{
    const float* x       = (const float*)d_in[0];
    const float* y       = (const float*)d_in[1];
    const float* ln_kv_w = (const float*)d_in[2];
    const float* ln_kv_b = (const float*)d_in[3];
    const float* ln_q_w  = (const float*)d_in[4];
    const float* ln_q_b  = (const float*)d_in[5];
    const float* W_kv    = (const float*)d_in[6];
    const float* W_dw    = (const float*)d_in[7];
    const float* W_q     = (const float*)d_in[8];
    const float* W_proj  = (const float*)d_in[9];
    const float* temp    = (const float*)d_in[10];
    float* out = (float*)d_out;

    __nv_bfloat16 *p_xn, *p_imq, *p_avb, *p_Wkv, *p_Wq, *p_Wp, *p_kvb, *p_qb;
    float *p_yn, *p_sumq;
    cudaGetSymbolAddress((void**)&p_xn,   g_xn);
    cudaGetSymbolAddress((void**)&p_imq,  g_imq);
    cudaGetSymbolAddress((void**)&p_avb,  g_avb);
    cudaGetSymbolAddress((void**)&p_Wkv,  g_Wkv);
    cudaGetSymbolAddress((void**)&p_Wq,   g_Wq);
    cudaGetSymbolAddress((void**)&p_Wp,   g_Wp);
    cudaGetSymbolAddress((void**)&p_kvb,  g_kvb);
    cudaGetSymbolAddress((void**)&p_qb,   g_qb);
    cudaGetSymbolAddress((void**)&p_yn,   g_yn);
    cudaGetSymbolAddress((void**)&p_sumq, g_sumq);

    const int SMEM = 98304;
    cudaFuncSetAttribute(gemm_hmma<true,false>,  cudaFuncAttributeMaxDynamicSharedMemorySize, SMEM);
    cudaFuncSetAttribute(gemm_hmma<true,true>,   cudaFuncAttributeMaxDynamicSharedMemorySize, SMEM);
    cudaFuncSetAttribute(gemm_hmma<false,false>, cudaFuncAttributeMaxDynamicSharedMemorySize, SMEM);

    convw_kernel<<<3080, 256>>>(W_kv, W_q, W_proj);
    ln_kernel<<<dim3(256,2), 256>>>(x, y, ln_kv_w, ln_kv_b, ln_q_w, ln_q_b);
    shift9_kernel<<<dim3(72, CC, BB), 256>>>();
    // kv = W_kv @ xn   (M=512, K=256) -> bf16
    gemm_hmma<true,false><<<dim3(4, 256, BB), 256, SMEM>>>(p_Wkv, p_xn, nullptr, p_kvb, nullptr, CC, 2*CC);
    dw_kernel<<<16384, 256>>>(W_dw);
    // q = W_q(3x3) @ yn via im2col  (M=256, K=2304) -> bf16 + q-norm sums
    gemm_hmma<true,true><<<dim3(2, 256, BB), 256, SMEM>>>(p_Wq, p_imq, nullptr, p_qb, p_sumq, KQ, CC);
    attn_part_kernel<<<dim3(8,32), 256>>>();
    softmax_kernel<<<32, 1024>>>(temp);
    av_kernel<<<dim3(128,32), 128>>>();
    // out = yn + W_proj @ av  (M=256, K=256, residual) -> fp32
    gemm_hmma<false,false><<<dim3(2, 256, BB), 256, SMEM>>>(p_Wp, p_avb, p_yn, out, nullptr, CC, CC);
}